// round 6
// baseline (speedup 1.0000x reference)
#include <cuda_runtime.h>
#include <cstdint>

// ---------------------------------------------------------------------------
// GCN: out = L3(relu(L2(relu(L1(x)))))   symmetric norm + self loops.
//   msg_L = (x_L @ W_L) * dinv          x_L = relu(agg_{L-1}*dinv + b_{L-1})
//   agg_{L-1}[n] = msg_{L-1}[n] + sum_{(s,n) in E} msg_{L-1}[s]
// Fused: gather of agg happens inside the next layer's GEMM prologue; agg is
// never materialized. Final layer's gather fuses the b3/dinv epilogue.
// ---------------------------------------------------------------------------

static constexpr int NMAX = 100000;
static constexpr int D    = 64;
static constexpr int CAP  = 96;     // max in-degree bucket (Poisson(16): safe)

__device__ float g_dinv [NMAX];
__device__ int   g_count[NMAX];
__device__ int   g_csrc [NMAX * CAP];
__device__ float g_msgA [NMAX * D];
__device__ float g_msgB [NMAX * D];

__device__ __forceinline__ float4 f4add(float4 a, float4 b) {
    return make_float4(a.x + b.x, a.y + b.y, a.z + b.z, a.w + b.w);
}

// ---------------------------------------------------------------------------
// CSR build
// ---------------------------------------------------------------------------
__global__ void k_zero(int N) {
    int i = blockIdx.x * blockDim.x + threadIdx.x;
    if (i < N) g_count[i] = 0;
}

__global__ void k_fill(const int* __restrict__ src, const int* __restrict__ dst,
                       int E) {
    int e = blockIdx.x * blockDim.x + threadIdx.x;
    if (e >= E) return;
    int s = __ldg(src + e);
    int d = __ldg(dst + e);
    int pos = atomicAdd(&g_count[d], 1);
    if (pos < CAP) g_csrc[d * CAP + pos] = s;
}

__global__ void k_dinv(int N) {
    int i = blockIdx.x * blockDim.x + threadIdx.x;
    if (i < N) g_dinv[i] = rsqrtf((float)g_count[i] + 1.0f);
}

// ---------------------------------------------------------------------------
// Gather helper: acc = msg[node] + sum_{s in bucket(node)} msg[s]   (col c)
// ---------------------------------------------------------------------------
__device__ __forceinline__ float4
gather_node(const float4* __restrict__ msg4, int node, int c)
{
    int cnt = g_count[node];
    if (cnt > CAP) cnt = CAP;
    const int* lst = g_csrc + (size_t)node * CAP;
    float4 acc = msg4[(size_t)node * 16 + c];        // self loop
    int i = 0;
    for (; i + 4 <= cnt; i += 4) {
        int s0 = __ldg(lst + i);
        int s1 = __ldg(lst + i + 1);
        int s2 = __ldg(lst + i + 2);
        int s3 = __ldg(lst + i + 3);
        float4 a = msg4[(size_t)s0 * 16 + c];
        float4 b = msg4[(size_t)s1 * 16 + c];
        float4 cc = msg4[(size_t)s2 * 16 + c];
        float4 dd = msg4[(size_t)s3 * 16 + c];
        acc = f4add(f4add(acc, a), f4add(b, cc));
        acc = f4add(acc, dd);
    }
    for (; i < cnt; i++) {
        int s0 = __ldg(lst + i);
        acc = f4add(acc, msg4[(size_t)s0 * 16 + c]);
    }
    return acc;
}

// ---------------------------------------------------------------------------
// Fused layer: x = ext  OR  relu(gather(msg_in)*dinv + b_prev)
//              msg_out = (x @ W) * dinv
// 128-row tile, 256 threads, each thread 8 rows x 4 cols.
// ---------------------------------------------------------------------------
__global__ void __launch_bounds__(256)
k_layer(const float* __restrict__ xin_ext,  // non-null: layer 1 (no gather)
        int in_buf,                         // msg to gather from (0=A,1=B)
        const float* __restrict__ W,
        const float* __restrict__ b_prev,
        int out_buf,                        // msg to write       (0=A,1=B)
        int N)
{
    __shared__ float xsT[64 * 128];         // [k][row] swizzled, 32 KB
    __shared__ float Ws [64 * 64];          // 16 KB (48 KB total)

    const int tid  = threadIdx.x;
    const int row0 = blockIdx.x * 128;

    // Load W: 1024 float4, 4 per thread.
    {
        const float4* W4 = (const float4*)W;
        float4* Wl = (float4*)Ws;
        #pragma unroll
        for (int i = 0; i < 4; i++) Wl[tid + i * 256] = W4[tid + i * 256];
    }

    const float* msg_in = in_buf ? g_msgB : g_msgA;
    const float4* min4  = (const float4*)msg_in;

    // Prologue: build x tile (gather + activation fused), store transposed
    // with XOR swizzle: float4 group e=row>>2 at slot e^((k>>3)&7).
    #pragma unroll
    for (int it = 0; it < 8; it++) {
        int r   = it * 16 + (tid >> 4);     // local row 0..127
        int c   = tid & 15;                 // float4 col group
        int row = row0 + r;
        float4 v = make_float4(0.f, 0.f, 0.f, 0.f);
        if (row < N) {
            if (xin_ext) {
                v = ((const float4*)xin_ext)[(size_t)row * 16 + c];
            } else {
                float4 acc = gather_node(min4, row, c);
                float  s   = g_dinv[row];
                float4 b   = ((const float4*)b_prev)[c];
                v.x = fmaxf(fmaf(acc.x, s, b.x), 0.f);
                v.y = fmaxf(fmaf(acc.y, s, b.y), 0.f);
                v.z = fmaxf(fmaf(acc.z, s, b.z), 0.f);
                v.w = fmaxf(fmaf(acc.w, s, b.w), 0.f);
            }
        }
        float vv[4] = {v.x, v.y, v.z, v.w};
        int e = r >> 2, rq = r & 3;
        #pragma unroll
        for (int q = 0; q < 4; q++) {
            int k  = c * 4 + q;
            int sw = (k >> 3) & 7;
            xsT[k * 128 + ((e ^ sw) << 2) + rq] = vv[q];
        }
    }
    __syncthreads();

    const int rg = tid >> 4;                // 0..15 row group (8 rows)
    const int cg = tid & 15;                // 0..15 col group (4 cols)
    const int e0 = rg * 2;

    float4 acc[8];
    #pragma unroll
    for (int i = 0; i < 8; i++) acc[i] = make_float4(0.f, 0.f, 0.f, 0.f);

    const float4* xs4 = (const float4*)xsT;
    const float4* Ws4 = (const float4*)Ws;

    #pragma unroll 8
    for (int k = 0; k < 64; k++) {
        int sw = (k >> 3) & 7;
        float4 xa = xs4[k * 32 + (e0 ^ sw)];
        float4 xb = xs4[k * 32 + ((e0 + 1) ^ sw)];
        float4 w  = Ws4[k * 16 + cg];
        acc[0].x = fmaf(xa.x, w.x, acc[0].x); acc[0].y = fmaf(xa.x, w.y, acc[0].y);
        acc[0].z = fmaf(xa.x, w.z, acc[0].z); acc[0].w = fmaf(xa.x, w.w, acc[0].w);
        acc[1].x = fmaf(xa.y, w.x, acc[1].x); acc[1].y = fmaf(xa.y, w.y, acc[1].y);
        acc[1].z = fmaf(xa.y, w.z, acc[1].z); acc[1].w = fmaf(xa.y, w.w, acc[1].w);
        acc[2].x = fmaf(xa.z, w.x, acc[2].x); acc[2].y = fmaf(xa.z, w.y, acc[2].y);
        acc[2].z = fmaf(xa.z, w.z, acc[2].z); acc[2].w = fmaf(xa.z, w.w, acc[2].w);
        acc[3].x = fmaf(xa.w, w.x, acc[3].x); acc[3].y = fmaf(xa.w, w.y, acc[3].y);
        acc[3].z = fmaf(xa.w, w.z, acc[3].z); acc[3].w = fmaf(xa.w, w.w, acc[3].w);
        acc[4].x = fmaf(xb.x, w.x, acc[4].x); acc[4].y = fmaf(xb.x, w.y, acc[4].y);
        acc[4].z = fmaf(xb.x, w.z, acc[4].z); acc[4].w = fmaf(xb.x, w.w, acc[4].w);
        acc[5].x = fmaf(xb.y, w.x, acc[5].x); acc[5].y = fmaf(xb.y, w.y, acc[5].y);
        acc[5].z = fmaf(xb.y, w.z, acc[5].z); acc[5].w = fmaf(xb.y, w.w, acc[5].w);
        acc[6].x = fmaf(xb.z, w.x, acc[6].x); acc[6].y = fmaf(xb.z, w.y, acc[6].y);
        acc[6].z = fmaf(xb.z, w.z, acc[6].z); acc[6].w = fmaf(xb.z, w.w, acc[6].w);
        acc[7].x = fmaf(xb.w, w.x, acc[7].x); acc[7].y = fmaf(xb.w, w.y, acc[7].y);
        acc[7].z = fmaf(xb.w, w.z, acc[7].z); acc[7].w = fmaf(xb.w, w.w, acc[7].w);
    }

    // Epilogue: msg_out = acc * dinv[row]
    float* msg_out = out_buf ? g_msgB : g_msgA;
    const int r0 = rg * 8;
    #pragma unroll
    for (int i = 0; i < 8; i++) {
        int row = row0 + r0 + i;
        if (row < N) {
            float s = g_dinv[row];
            ((float4*)msg_out)[(size_t)row * 16 + cg] =
                make_float4(acc[i].x * s, acc[i].y * s,
                            acc[i].z * s, acc[i].w * s);
        }
    }
}

// ---------------------------------------------------------------------------
// Final: out = gather(msg3)*dinv + b3     (fused gather + epilogue, no relu)
// ---------------------------------------------------------------------------
__global__ void __launch_bounds__(256)
k_out(float* __restrict__ out, const float* __restrict__ b3,
      int in_buf, int N)
{
    int t = blockIdx.x * blockDim.x + threadIdx.x;
    if (t >= N * 16) return;
    int node = t >> 4;
    int c    = t & 15;
    const float4* min4 = (const float4*)(in_buf ? g_msgB : g_msgA);

    float4 acc = gather_node(min4, node, c);
    float  s   = g_dinv[node];
    float4 b   = ((const float4*)b3)[c];
    acc.x = fmaf(acc.x, s, b.x);
    acc.y = fmaf(acc.y, s, b.y);
    acc.z = fmaf(acc.z, s, b.z);
    acc.w = fmaf(acc.w, s, b.w);
    ((float4*)out)[t] = acc;
}

// ---------------------------------------------------------------------------
// Launch
// ---------------------------------------------------------------------------
extern "C" void kernel_launch(void* const* d_in, const int* in_sizes, int n_in,
                              void* d_out, int out_size)
{
    const float* node_embed = (const float*)d_in[0];
    const int*   edges      = (const int*)d_in[1];
    const float* W1 = (const float*)d_in[2];
    const float* b1 = (const float*)d_in[3];
    const float* W2 = (const float*)d_in[4];
    const float* b2 = (const float*)d_in[5];
    const float* W3 = (const float*)d_in[6];
    const float* b3 = (const float*)d_in[7];
    float* out = (float*)d_out;

    const int N = in_sizes[0] / D;
    const int E = in_sizes[1] / 2;
    const int* src = edges;
    const int* dst = edges + E;

    const int TB = 256;
    dim3 blk(TB);

    // CSR build + dinv
    k_zero<<<(N + TB - 1) / TB, blk>>>(N);
    k_fill<<<(E + TB - 1) / TB, blk>>>(src, dst, E);
    k_dinv<<<(N + TB - 1) / TB, blk>>>(N);

    const int layer_blocks = (N + 127) / 128;

    // Layer 1: x = node_embed           -> msgA
    k_layer<<<layer_blocks, blk>>>(node_embed, 0, W1, nullptr, 0, N);
    // Layer 2: x = relu(gather(msgA)*dinv + b1) -> msgB
    k_layer<<<layer_blocks, blk>>>(nullptr, 0, W2, b1, 1, N);
    // Layer 3: x = relu(gather(msgB)*dinv + b2) -> msgA
    k_layer<<<layer_blocks, blk>>>(nullptr, 1, W3, b2, 0, N);
    // out = gather(msgA)*dinv + b3
    k_out<<<(N * 16 + TB - 1) / TB, blk>>>(out, b3, 0, N);
}

// round 7
// speedup vs baseline: 1.1215x; 1.1215x over previous
#include <cuda_runtime.h>
#include <cstdint>

// ---------------------------------------------------------------------------
// GCN: out = L3(relu(L2(relu(L1(x)))))   symmetric norm + self loops.
//   g = (x @ W) * dinv[row]               (GEMM epilogue)
//   agg[n] = g[n] + sum_{(s,n) in E} g[s] (separate CSR gather: latency hidden
//                                          by N*16 independent threads)
//   next_x = relu(agg*dinv + b)           (next GEMM prologue)
// Final layer: gather fused with b3/dinv epilogue straight into d_out.
// ---------------------------------------------------------------------------

static constexpr int NMAX = 100000;
static constexpr int D    = 64;
static constexpr int CAP  = 96;     // max in-degree bucket (Poisson(16): safe)

__device__ float g_dinv [NMAX];
__device__ int   g_count[NMAX];
__device__ int   g_csrc [NMAX * CAP];
__device__ float g_msg  [NMAX * D];
__device__ float g_aggA [NMAX * D];
__device__ float g_aggB [NMAX * D];

__device__ __forceinline__ float4 f4add(float4 a, float4 b) {
    return make_float4(a.x + b.x, a.y + b.y, a.z + b.z, a.w + b.w);
}

// ---------------------------------------------------------------------------
// CSR build
// ---------------------------------------------------------------------------
__global__ void k_zero(int N) {
    int i = blockIdx.x * blockDim.x + threadIdx.x;
    if (i < N) g_count[i] = 0;
}

__global__ void k_fill(const int* __restrict__ src, const int* __restrict__ dst,
                       int E) {
    int e = blockIdx.x * blockDim.x + threadIdx.x;
    if (e >= E) return;
    int s = __ldg(src + e);
    int d = __ldg(dst + e);
    int pos = atomicAdd(&g_count[d], 1);
    if (pos < CAP) g_csrc[d * CAP + pos] = s;
}

__global__ void k_dinv(int N) {
    int i = blockIdx.x * blockDim.x + threadIdx.x;
    if (i < N) g_dinv[i] = rsqrtf((float)g_count[i] + 1.0f);
}

// ---------------------------------------------------------------------------
// Gather helper: acc = msg[node] + sum_{s in bucket(node)} msg[s]   (col c)
// ---------------------------------------------------------------------------
__device__ __forceinline__ float4
gather_node(const float4* __restrict__ msg4, int node, int c)
{
    int cnt = g_count[node];
    if (cnt > CAP) cnt = CAP;
    const int* lst = g_csrc + (size_t)node * CAP;
    float4 acc = msg4[(size_t)node * 16 + c];        // self loop
    int i = 0;
    for (; i + 4 <= cnt; i += 4) {
        int s0 = __ldg(lst + i);
        int s1 = __ldg(lst + i + 1);
        int s2 = __ldg(lst + i + 2);
        int s3 = __ldg(lst + i + 3);
        float4 a = msg4[(size_t)s0 * 16 + c];
        float4 b = msg4[(size_t)s1 * 16 + c];
        float4 cc = msg4[(size_t)s2 * 16 + c];
        float4 dd = msg4[(size_t)s3 * 16 + c];
        acc = f4add(f4add(acc, a), f4add(b, cc));
        acc = f4add(acc, dd);
    }
    for (; i < cnt; i++) {
        int s0 = __ldg(lst + i);
        acc = f4add(acc, msg4[(size_t)s0 * 16 + c]);
    }
    return acc;
}

// ---------------------------------------------------------------------------
// GEMM: 128-row tile, 256 threads, 8 rows x 4 cols per thread.
// x tile transposed + XOR-swizzled; per k: 2 LDS.128 (x) + 1 LDS.128 (W).
// ---------------------------------------------------------------------------
__global__ void __launch_bounds__(256, 3)
k_gemm(const float* __restrict__ xin_ext,   // non-null for layer 1
       int in_buf,                          // agg buffer to read (if internal)
       const float* __restrict__ W,
       const float* __restrict__ b_prev,    // prev-layer bias (internal mode)
       int N)
{
    __shared__ float xsT[64 * 128];         // [k][row] swizzled, 32 KB
    __shared__ float Ws [64 * 64];          // 16 KB (48 KB total)

    const int tid  = threadIdx.x;
    const int row0 = blockIdx.x * 128;

    // Load W: 1024 float4, 4 per thread.
    {
        const float4* W4 = (const float4*)W;
        float4* Wl = (float4*)Ws;
        #pragma unroll
        for (int i = 0; i < 4; i++) Wl[tid + i * 256] = W4[tid + i * 256];
    }

    const float* xin = xin_ext ? xin_ext : (in_buf ? g_aggB : g_aggA);

    // Load x tile (128 rows x 16 float4), prev-layer epilogue on the fly,
    // store transposed with swizzle: group e=row>>2 at slot e^((k>>3)&7).
    #pragma unroll
    for (int it = 0; it < 8; it++) {
        int r   = it * 16 + (tid >> 4);     // local row 0..127
        int c4  = tid & 15;                 // float4 col group
        int row = row0 + r;
        float4 v = make_float4(0.f, 0.f, 0.f, 0.f);
        if (row < N) {
            v = ((const float4*)xin)[(size_t)row * 16 + c4];
            if (!xin_ext) {
                float s  = g_dinv[row];
                float4 b = ((const float4*)b_prev)[c4];
                v.x = fmaxf(fmaf(v.x, s, b.x), 0.f);
                v.y = fmaxf(fmaf(v.y, s, b.y), 0.f);
                v.z = fmaxf(fmaf(v.z, s, b.z), 0.f);
                v.w = fmaxf(fmaf(v.w, s, b.w), 0.f);
            }
        }
        float vv[4] = {v.x, v.y, v.z, v.w};
        int e = r >> 2, rq = r & 3;
        #pragma unroll
        for (int q = 0; q < 4; q++) {
            int k  = c4 * 4 + q;
            int sw = (k >> 3) & 7;
            xsT[k * 128 + ((e ^ sw) << 2) + rq] = vv[q];
        }
    }
    __syncthreads();

    const int rg = tid >> 4;                // 0..15 row group (8 rows)
    const int cg = tid & 15;                // 0..15 col group (4 cols)
    const int e0 = rg * 2;

    float4 acc[8];
    #pragma unroll
    for (int i = 0; i < 8; i++) acc[i] = make_float4(0.f, 0.f, 0.f, 0.f);

    const float4* xs4 = (const float4*)xsT;
    const float4* Ws4 = (const float4*)Ws;

    // Outer loop over swizzle groups: indices constant within a group of 8 k.
    #pragma unroll
    for (int kk = 0; kk < 8; kk++) {
        const int idxA = e0 ^ kk;
        const int idxB = (e0 + 1) ^ kk;
        #pragma unroll
        for (int ki = 0; ki < 8; ki++) {
            const int k = kk * 8 + ki;
            float4 xa = xs4[k * 32 + idxA];
            float4 xb = xs4[k * 32 + idxB];
            float4 w  = Ws4[k * 16 + cg];
            acc[0].x = fmaf(xa.x, w.x, acc[0].x); acc[0].y = fmaf(xa.x, w.y, acc[0].y);
            acc[0].z = fmaf(xa.x, w.z, acc[0].z); acc[0].w = fmaf(xa.x, w.w, acc[0].w);
            acc[1].x = fmaf(xa.y, w.x, acc[1].x); acc[1].y = fmaf(xa.y, w.y, acc[1].y);
            acc[1].z = fmaf(xa.y, w.z, acc[1].z); acc[1].w = fmaf(xa.y, w.w, acc[1].w);
            acc[2].x = fmaf(xa.z, w.x, acc[2].x); acc[2].y = fmaf(xa.z, w.y, acc[2].y);
            acc[2].z = fmaf(xa.z, w.z, acc[2].z); acc[2].w = fmaf(xa.z, w.w, acc[2].w);
            acc[3].x = fmaf(xa.w, w.x, acc[3].x); acc[3].y = fmaf(xa.w, w.y, acc[3].y);
            acc[3].z = fmaf(xa.w, w.z, acc[3].z); acc[3].w = fmaf(xa.w, w.w, acc[3].w);
            acc[4].x = fmaf(xb.x, w.x, acc[4].x); acc[4].y = fmaf(xb.x, w.y, acc[4].y);
            acc[4].z = fmaf(xb.x, w.z, acc[4].z); acc[4].w = fmaf(xb.x, w.w, acc[4].w);
            acc[5].x = fmaf(xb.y, w.x, acc[5].x); acc[5].y = fmaf(xb.y, w.y, acc[5].y);
            acc[5].z = fmaf(xb.y, w.z, acc[5].z); acc[5].w = fmaf(xb.y, w.w, acc[5].w);
            acc[6].x = fmaf(xb.z, w.x, acc[6].x); acc[6].y = fmaf(xb.z, w.y, acc[6].y);
            acc[6].z = fmaf(xb.z, w.z, acc[6].z); acc[6].w = fmaf(xb.z, w.w, acc[6].w);
            acc[7].x = fmaf(xb.w, w.x, acc[7].x); acc[7].y = fmaf(xb.w, w.y, acc[7].y);
            acc[7].z = fmaf(xb.w, w.z, acc[7].z); acc[7].w = fmaf(xb.w, w.w, acc[7].w);
        }
    }

    // Epilogue: g = acc * dinv[row] -> g_msg
    const int r0 = rg * 8;
    #pragma unroll
    for (int i = 0; i < 8; i++) {
        int row = row0 + r0 + i;
        if (row < N) {
            float s = g_dinv[row];
            ((float4*)g_msg)[(size_t)row * 16 + cg] =
                make_float4(acc[i].x * s, acc[i].y * s,
                            acc[i].z * s, acc[i].w * s);
        }
    }
}

// ---------------------------------------------------------------------------
// Gather (layers 1-2): agg[n] = self + neighbors.  16 threads per node.
// ---------------------------------------------------------------------------
__global__ void __launch_bounds__(256)
k_gather(int out_buf, int N)
{
    int t = blockIdx.x * blockDim.x + threadIdx.x;
    if (t >= N * 16) return;
    int node = t >> 4;
    int c    = t & 15;
    float* agg = out_buf ? g_aggB : g_aggA;
    float4 acc = gather_node((const float4*)g_msg, node, c);
    ((float4*)agg)[(size_t)node * 16 + c] = acc;
}

// ---------------------------------------------------------------------------
// Final: out = gather(msg)*dinv + b3    (fused gather + epilogue, no relu)
// ---------------------------------------------------------------------------
__global__ void __launch_bounds__(256)
k_out(float* __restrict__ out, const float* __restrict__ b3, int N)
{
    int t = blockIdx.x * blockDim.x + threadIdx.x;
    if (t >= N * 16) return;
    int node = t >> 4;
    int c    = t & 15;
    float4 acc = gather_node((const float4*)g_msg, node, c);
    float  s   = g_dinv[node];
    float4 b   = ((const float4*)b3)[c];
    acc.x = fmaf(acc.x, s, b.x);
    acc.y = fmaf(acc.y, s, b.y);
    acc.z = fmaf(acc.z, s, b.z);
    acc.w = fmaf(acc.w, s, b.w);
    ((float4*)out)[t] = acc;
}

// ---------------------------------------------------------------------------
// Launch
// ---------------------------------------------------------------------------
extern "C" void kernel_launch(void* const* d_in, const int* in_sizes, int n_in,
                              void* d_out, int out_size)
{
    const float* node_embed = (const float*)d_in[0];
    const int*   edges      = (const int*)d_in[1];
    const float* W1 = (const float*)d_in[2];
    const float* b1 = (const float*)d_in[3];
    const float* W2 = (const float*)d_in[4];
    const float* b2 = (const float*)d_in[5];
    const float* W3 = (const float*)d_in[6];
    const float* b3 = (const float*)d_in[7];
    float* out = (float*)d_out;

    const int N = in_sizes[0] / D;
    const int E = in_sizes[1] / 2;
    const int* src = edges;
    const int* dst = edges + E;

    // Raise smem carveout so 3 blocks of 48 KB fit per SM (host-side attr,
    // not a captured op; idempotent and deterministic).
    static bool attr_done = false;
    if (!attr_done) {
        cudaFuncSetAttribute(k_gemm,
            cudaFuncAttributePreferredSharedMemoryCarveout, 100);
        attr_done = true;
    }

    const int TB = 256;
    dim3 blk(TB);

    // CSR build + dinv
    k_zero<<<(N + TB - 1) / TB, blk>>>(N);
    k_fill<<<(E + TB - 1) / TB, blk>>>(src, dst, E);
    k_dinv<<<(N + TB - 1) / TB, blk>>>(N);

    const int gemm_blocks   = (N + 127) / 128;
    const int gather_blocks = (N * 16 + TB - 1) / TB;

    // Layer 1: x = node_embed -> msg; gather -> A
    k_gemm  <<<gemm_blocks, blk>>>(node_embed, 0, W1, nullptr, N);
    k_gather<<<gather_blocks, blk>>>(0, N);

    // Layer 2: x = relu(A*dinv + b1) -> msg; gather -> B
    k_gemm  <<<gemm_blocks, blk>>>(nullptr, 0, W2, b1, N);
    k_gather<<<gather_blocks, blk>>>(1, N);

    // Layer 3: x = relu(B*dinv + b2) -> msg; fused gather+epilogue -> out
    k_gemm  <<<gemm_blocks, blk>>>(nullptr, 1, W3, b2, N);
    k_out   <<<gather_blocks, blk>>>(out, b3, N);
}